// round 16
// baseline (speedup 1.0000x reference)
#include <cuda_runtime.h>
#include <cuda_bf16.h>

#define JAX_PARTITIONABLE 1

// ---------------- scratch (__device__ globals; no allocation) ----------------
__device__ float g_T[8192 * 128];          // X_in @ theta
__device__ float g_U[8192 * 128];          // xi @ w_trans0
__device__ float g_U1[8192 * 128];         // xi @ w_trans1
__device__ float g_msg[4096 * 128];        // edge messages (ew-scaled)
__device__ float g_msgP[4 * 4096 * 128];   // split-K partials, Hs GEMM (S=4)
__device__ float g_ZP[2 * 8192 * 128];     // split-K partials, Ht^T GEMM (S=2)
__device__ int   g_scaleMax[4];            // |max| slots: T0, msg0, T1, msg1

static const int ZP_STRIDE = 64 * 128 * 128;

// ------------------------------- helpers ------------------------------------
__device__ __forceinline__ unsigned rotl32(unsigned v, int s) {
    return __funnelshift_l(v, v, s);
}

__device__ __forceinline__ void split_pair(float f0, float f1,
                                           unsigned& H, unsigned& L) {
    __nv_bfloat162 h = __floats2bfloat162_rn(f0, f1);
    float r0 = f0 - __bfloat162float(h.x);
    float r1 = f1 - __bfloat162float(h.y);
    __nv_bfloat162 l = __floats2bfloat162_rn(r0, r1);
    H = *reinterpret_cast<unsigned*>(&h);
    L = *reinterpret_cast<unsigned*>(&l);
}

__device__ __forceinline__ void mma16(float c[4], const unsigned a[4], const unsigned b[2]) {
    asm("mma.sync.aligned.m16n8k16.row.col.f32.bf16.bf16.f32 "
        "{%0,%1,%2,%3},{%4,%5,%6,%7},{%8,%9},{%0,%1,%2,%3};"
        : "+f"(c[0]), "+f"(c[1]), "+f"(c[2]), "+f"(c[3])
        : "r"(a[0]), "r"(a[1]), "r"(a[2]), "r"(a[3]), "r"(b[0]), "r"(b[1]));
}

// s8 imma m16n8k32, s32 accumulate (2x bf16 rate on the legacy mma path)
__device__ __forceinline__ void imma32(int c[4], const unsigned a[4], const unsigned b[2]) {
    asm("mma.sync.aligned.m16n8k32.row.col.s32.s8.s8.s32 "
        "{%0,%1,%2,%3},{%4,%5,%6,%7},{%8,%9},{%0,%1,%2,%3};"
        : "+r"(c[0]), "+r"(c[1]), "+r"(c[2]), "+r"(c[3])
        : "r"(a[0]), "r"(a[1]), "r"(a[2]), "r"(a[3]), "r"(b[0]), "r"(b[1]));
}

// quantize 4 consecutive k-values to 2-digit s8: q0 = round(f*inv) in [-127,127],
// q1 = round((f*inv - q0)*256) clamped. Packs 4 digits per u32.
__device__ __forceinline__ void quant_quad(float v0, float v1, float v2, float v3,
                                           float inv, unsigned& q0, unsigned& q1) {
    float f0 = v0 * inv, f1 = v1 * inv, f2 = v2 * inv, f3 = v3 * inv;
    int a0 = __float2int_rn(f0), a1 = __float2int_rn(f1);
    int a2 = __float2int_rn(f2), a3 = __float2int_rn(f3);
    int r0 = min(127, __float2int_rn((f0 - (float)a0) * 256.f));
    int r1 = min(127, __float2int_rn((f1 - (float)a1) * 256.f));
    int r2 = min(127, __float2int_rn((f2 - (float)a2) * 256.f));
    int r3 = min(127, __float2int_rn((f3 - (float)a3) * 256.f));
    q0 = (a0 & 0xFF) | ((a1 & 0xFF) << 8) | ((a2 & 0xFF) << 16) | ((a3 & 0xFF) << 24);
    q1 = (r0 & 0xFF) | ((r1 & 0xFF) << 8) | ((r2 & 0xFF) << 16) | ((r3 & 0xFF) << 24);
}

// JAX threefry2x32, key = (0, 42).
__device__ __forceinline__ unsigned jax_dropout_bits(unsigned j) {
    const unsigned k0 = 0u, k1 = 42u;
    const unsigned ks2 = k0 ^ k1 ^ 0x1BD11BDAu;
    unsigned x0, x1;
#if JAX_PARTITIONABLE
    x0 = 0u + k0;
    x1 = j + k1;
#else
    const unsigned HALF = 524288u;
    unsigned i = (j < HALF) ? j : (j - HALF);
    x0 = i + k0;
    x1 = (i + HALF) + k1;
#endif
#define TFR(r) do { x0 += x1; x1 = rotl32(x1, (r)); x1 ^= x0; } while (0)
    TFR(13); TFR(15); TFR(26); TFR(6);   x0 += k1;  x1 += ks2 + 1u;
    TFR(17); TFR(29); TFR(16); TFR(24);  x0 += ks2; x1 += k0 + 2u;
    TFR(13); TFR(15); TFR(26); TFR(6);   x0 += k0;  x1 += k1 + 3u;
    TFR(17); TFR(29); TFR(16); TFR(24);  x0 += k1;  x1 += ks2 + 4u;
    TFR(13); TFR(15); TFR(26); TFR(6);   x0 += ks2; x1 += k0 + 5u;
#undef TFR
#if JAX_PARTITIONABLE
    return x0 ^ x1;
#else
    return (j < 524288u) ? x0 : x1;
#endif
}

// fused X1 element build
__device__ __forceinline__ float4 make_x1(const float* __restrict__ ZP,
                                          const float* __restrict__ U,
                                          const float* __restrict__ bias,
                                          int idx, int col)
{
    float4 u  = *(const float4*)(U + idx);
    float4 p0 = *(const float4*)(ZP + idx);
    float4 p1 = *(const float4*)(ZP + ZP_STRIDE + idx);
    float e[4] = { u.x + bias[col],     u.y + bias[col + 1],
                   u.z + bias[col + 2], u.w + bias[col + 3] };
    e[0] += p0.x; e[1] += p0.y; e[2] += p0.z; e[3] += p0.w;
    e[0] += p1.x; e[1] += p1.y; e[2] += p1.z; e[3] += p1.w;
    float4 r;
    float* rr = &r.x;
#pragma unroll
    for (int q = 0; q < 4; ++q) {
        float z = e[q];
        z = (z >= 0.f) ? z : 0.01f * z;
        unsigned bits = jax_dropout_bits((unsigned)(idx + q));
        rr[q] = (bits & 0x80000000u) ? 0.f : (z + z);
    }
    return r;
}

// ==================== INT8 2-digit big GEMM (k32/iter) =======================
// C[M,128] = op(A) @ B.  A in [0,1) (s_A = 1), B scaled by *sBp (|max|).
// 512 threads = 16 warps (4M x 4N), warp tile 32x32.
// SMEM per buffer (u32): A0[128][12] | A1[128][12] | B0[8][136] | B1[8][136]
static const int QA = 12;
static const int QASZ = 128 * QA;              // 1536
static const int QBSZ = 8 * 136;               // 1088
static const int QBUF = 2 * QASZ + 2 * QBSZ;   // 5248 u32
// static smem: 2 * QBUF * 4 = 41984 B  (< 48KB, no opt-in needed)

template <bool TRANS_A>
__global__ __launch_bounds__(512, 1)
void gemm_i8(const float* __restrict__ A, const float* __restrict__ B,
             float* __restrict__ Cp, int lda, int k_iters,
             const int* __restrict__ sBp)
{
    __shared__ __align__(16) unsigned sm[2 * QBUF];
    const int tid = threadIdx.x;
    const int lane = tid & 31;
    const int wid = tid >> 5;
    const int wm = (wid & 3) * 32;
    const int wn = (wid >> 2) * 32;
    const int g = lane >> 2;
    const int t = lane & 3;
    const int m0 = blockIdx.x * 128;
    const int gx = gridDim.x;
    const int split = blockIdx.y;
    const int k00 = split * k_iters * 32;

    const float sB = fmaxf(__int_as_float(*sBp), 1e-30f);
    const float invB = 127.f / sB;

    // A staging tasks: 1024 (row, quad) pairs -> 2 per thread
    int a_row[2], a_q[2];
#pragma unroll
    for (int r = 0; r < 2; ++r) {
        int id = tid + r * 512;
        if (TRANS_A) { a_row[r] = id & 127; a_q[r] = id >> 7; }
        else         { a_row[r] = id >> 3;  a_q[r] = id & 7;  }
    }
    // B staging: tid < 256: task (q, n4)
    const int b_q = tid >> 5;            // 0..15 -> only <8 valid when tid<256
    const int b_n4 = tid & 31;
    const bool doB = (tid < 256);

    int accH[2][4][4], accM[2][4][4];
#pragma unroll
    for (int mt = 0; mt < 2; ++mt)
#pragma unroll
        for (int nt = 0; nt < 4; ++nt)
#pragma unroll
            for (int i = 0; i < 4; ++i) { accH[mt][nt][i] = 0; accM[mt][nt][i] = 0; }

    float4 av[2];
    float bwv[4][4];

    // ---- load tile 0 ----
    int kc = k00;
#pragma unroll
    for (int r = 0; r < 2; ++r) {
        if (TRANS_A) {
            const float* p = A + (size_t)(kc + a_q[r] * 4) * lda + m0 + a_row[r];
            av[r] = make_float4(p[0], p[(size_t)lda], p[2 * (size_t)lda], p[3 * (size_t)lda]);
        } else {
            av[r] = *(const float4*)(A + (size_t)(m0 + a_row[r]) * lda + kc + a_q[r] * 4);
        }
    }
    if (doB) {
#pragma unroll
        for (int j = 0; j < 4; ++j) {
            float4 v = *(const float4*)(B + (size_t)(kc + b_q * 4 + j) * 128 + b_n4 * 4);
            bwv[j][0] = v.x; bwv[j][1] = v.y; bwv[j][2] = v.z; bwv[j][3] = v.w;
        }
    }

    for (int it = 0; it < k_iters; ++it) {
        // stage current tile into buffer (it & 1)
        unsigned* buf = sm + (it & 1) * QBUF;
        unsigned* A0t = buf;
        unsigned* A1t = buf + QASZ;
        unsigned* B0t = buf + 2 * QASZ;
        unsigned* B1t = buf + 2 * QASZ + QBSZ;
#pragma unroll
        for (int r = 0; r < 2; ++r) {
            unsigned q0, q1;
            quant_quad(av[r].x, av[r].y, av[r].z, av[r].w, 127.f, q0, q1);
            A0t[a_row[r] * QA + a_q[r]] = q0;
            A1t[a_row[r] * QA + a_q[r]] = q1;
        }
        if (doB) {
            unsigned h[4], l[4];
#pragma unroll
            for (int c = 0; c < 4; ++c)
                quant_quad(bwv[0][c], bwv[1][c], bwv[2][c], bwv[3][c], invB, h[c], l[c]);
            *(uint4*)&B0t[b_q * 136 + b_n4 * 4] = make_uint4(h[0], h[1], h[2], h[3]);
            *(uint4*)&B1t[b_q * 136 + b_n4 * 4] = make_uint4(l[0], l[1], l[2], l[3]);
        }
        __syncthreads();

        // prefetch next tile (hidden under immas)
        const bool hn = (it + 1 < k_iters);
        if (hn) {
            kc = k00 + (it + 1) * 32;
#pragma unroll
            for (int r = 0; r < 2; ++r) {
                if (TRANS_A) {
                    const float* p = A + (size_t)(kc + a_q[r] * 4) * lda + m0 + a_row[r];
                    av[r] = make_float4(p[0], p[(size_t)lda], p[2 * (size_t)lda], p[3 * (size_t)lda]);
                } else {
                    av[r] = *(const float4*)(A + (size_t)(m0 + a_row[r]) * lda + kc + a_q[r] * 4);
                }
            }
            if (doB) {
#pragma unroll
                for (int j = 0; j < 4; ++j) {
                    float4 v = *(const float4*)(B + (size_t)(kc + b_q * 4 + j) * 128 + b_n4 * 4);
                    bwv[j][0] = v.x; bwv[j][1] = v.y; bwv[j][2] = v.z; bwv[j][3] = v.w;
                }
            }
        }

        // ---- compute on current buffer ----
        {
            const unsigned* cA0 = sm + (it & 1) * QBUF;
            const unsigned* cA1 = cA0 + QASZ;
            const unsigned* cB0 = cA0 + 2 * QASZ;
            const unsigned* cB1 = cA0 + 2 * QASZ + QBSZ;
            unsigned a0f[2][4], a1f[2][4];
#pragma unroll
            for (int mt = 0; mt < 2; ++mt) {
                const int r0 = (wm + mt * 16 + g) * QA;
                const int r1 = r0 + 8 * QA;
                a0f[mt][0] = cA0[r0 + t];     a0f[mt][1] = cA0[r1 + t];
                a0f[mt][2] = cA0[r0 + t + 4]; a0f[mt][3] = cA0[r1 + t + 4];
                a1f[mt][0] = cA1[r0 + t];     a1f[mt][1] = cA1[r1 + t];
                a1f[mt][2] = cA1[r0 + t + 4]; a1f[mt][3] = cA1[r1 + t + 4];
            }
#pragma unroll
            for (int nt = 0; nt < 4; ++nt) {
                const int nb = wn + nt * 8 + g;
                unsigned b0f[2] = { cB0[t * 136 + nb], cB0[(t + 4) * 136 + nb] };
                unsigned b1f[2] = { cB1[t * 136 + nb], cB1[(t + 4) * 136 + nb] };
#pragma unroll
                for (int mt = 0; mt < 2; ++mt) {
                    imma32(accH[mt][nt], a0f[mt], b0f);   // hi*hi
                    imma32(accM[mt][nt], a0f[mt], b1f);   // hi*lo
                    imma32(accM[mt][nt], a1f[mt], b0f);   // lo*hi
                }
            }
        }
        __syncthreads();
    }

    // epilogue: combine digits -> fp32 partial tile
    const float sc  = sB / (127.f * 127.f);
    const float scm = sc / 256.f;
    float* Cb = Cp + (size_t)split * gx * (128 * 128) + (size_t)m0 * 128;
#pragma unroll
    for (int mt = 0; mt < 2; ++mt)
#pragma unroll
        for (int nt = 0; nt < 4; ++nt) {
            const int r = wm + mt * 16 + g;
            const int c = wn + nt * 8 + t * 2;
            float v0 = sc * (float)accH[mt][nt][0] + scm * (float)accM[mt][nt][0];
            float v1 = sc * (float)accH[mt][nt][1] + scm * (float)accM[mt][nt][1];
            float v2 = sc * (float)accH[mt][nt][2] + scm * (float)accM[mt][nt][2];
            float v3 = sc * (float)accH[mt][nt][3] + scm * (float)accM[mt][nt][3];
            *(float2*)&Cb[(size_t)r * 128 + c] = make_float2(v0, v1);
            *(float2*)&Cb[(size_t)(r + 8) * 128 + c] = make_float2(v2, v3);
        }
}

// ================= bf16 3-term GEMM (small shapes, K=128) ====================
static const int ASZ = 4608, BSZ = 4352;
static const int BUF_STRIDE = 2 * ASZ + 2 * BSZ;
static const int SM_BYTES = BUF_STRIDE * 2 * 4;    // 143360 B

__device__ __forceinline__ void stA(unsigned* __restrict__ AsH,
                                    unsigned* __restrict__ AsL,
                                    int row, int kq, float4 v) {
    unsigned h0, l0, h1, l1;
    split_pair(v.x, v.y, h0, l0);
    split_pair(v.z, v.w, h1, l1);
    *(uint2*)&AsH[row * 36 + 2 * kq] = make_uint2(h0, h1);
    *(uint2*)&AsL[row * 36 + 2 * kq] = make_uint2(l0, l1);
}

__device__ __forceinline__ void stB(unsigned* __restrict__ BsH,
                                    unsigned* __restrict__ BsL,
                                    int p, int n, float4 r0, float4 r1) {
    unsigned h[4], l[4];
    split_pair(r0.x, r1.x, h[0], l[0]);
    split_pair(r0.y, r1.y, h[1], l[1]);
    split_pair(r0.z, r1.z, h[2], l[2]);
    split_pair(r0.w, r1.w, h[3], l[3]);
    *(uint4*)&BsH[p * 136 + n] = make_uint4(h[0], h[1], h[2], h[3]);
    *(uint4*)&BsL[p * 136 + n] = make_uint4(l[0], l[1], l[2], l[3]);
}

// A_SRC: 0 = plain global, 1 = fused X1 build. maxSlot: optional |max| tracker.
template <int A_SRC>
__device__ __forceinline__ void gemm_body_bf(
    const float* __restrict__ A, const float* __restrict__ B,
    float* __restrict__ Cp, int mblk,
    const float* __restrict__ xU, const float* __restrict__ xb,
    int* __restrict__ maxSlot)
{
    extern __shared__ unsigned smd[];
    const int lda = 128, k_iters = 2;
    const int tid = threadIdx.x;
    const int lane = tid & 31;
    const int wid = tid >> 5;
    const int wm = (wid & 3) * 32;
    const int wn = (wid >> 2) * 32;
    const int g = lane >> 2;
    const int t = lane & 3;
    const int m0 = mblk * 128;

    int ar_row[4], ar_kq[4];
#pragma unroll
    for (int r = 0; r < 4; ++r) {
        int task = tid + r * 512;
        ar_row[r] = task >> 4;  ar_kq[r] = task & 15;
    }
    int b_p[2], b_n[2];
#pragma unroll
    for (int r = 0; r < 2; ++r) {
        int task = tid + r * 512;
        b_p[r] = task >> 5;
        b_n[r] = (task & 31) * 4;
    }

    float acc[2][4][4];
#pragma unroll
    for (int mt = 0; mt < 2; ++mt)
#pragma unroll
        for (int nt = 0; nt < 4; ++nt)
#pragma unroll
            for (int i = 0; i < 4; ++i) acc[mt][nt][i] = 0.f;

    float4 av[4], bv0[2], bv1[2];
    int kc = 0;
#pragma unroll
    for (int r = 0; r < 4; ++r) {
        if (A_SRC == 1)
            av[r] = make_x1(A, xU, xb, (m0 + ar_row[r]) * 128 + kc + ar_kq[r] * 4,
                            kc + ar_kq[r] * 4);
        else
            av[r] = *(const float4*)(A + (size_t)(m0 + ar_row[r]) * lda + kc + ar_kq[r] * 4);
    }
#pragma unroll
    for (int r = 0; r < 2; ++r) {
        bv0[r] = *(const float4*)(B + (size_t)(kc + 2 * b_p[r]) * 128 + b_n[r]);
        bv1[r] = *(const float4*)(B + (size_t)(kc + 2 * b_p[r] + 1) * 128 + b_n[r]);
    }
#pragma unroll
    for (int r = 0; r < 4; ++r) stA(smd, smd + ASZ, ar_row[r], ar_kq[r], av[r]);
#pragma unroll
    for (int r = 0; r < 2; ++r)
        stB(smd + 2 * ASZ, smd + 2 * ASZ + BSZ, b_p[r], b_n[r], bv0[r], bv1[r]);
    __syncthreads();

    for (int it = 0; it < k_iters; ++it) {
        const unsigned* cur = smd + (it & 1) * BUF_STRIDE;
        const unsigned* cAH = cur;
        const unsigned* cAL = cur + ASZ;
        const unsigned* cBH = cur + 2 * ASZ;
        const unsigned* cBL = cur + 2 * ASZ + BSZ;
        const bool hn = (it + 1 < k_iters);

        if (hn) {
            kc = (it + 1) * 64;
#pragma unroll
            for (int r = 0; r < 4; ++r) {
                if (A_SRC == 1)
                    av[r] = make_x1(A, xU, xb, (m0 + ar_row[r]) * 128 + kc + ar_kq[r] * 4,
                                    kc + ar_kq[r] * 4);
                else
                    av[r] = *(const float4*)(A + (size_t)(m0 + ar_row[r]) * lda + kc + ar_kq[r] * 4);
            }
#pragma unroll
            for (int r = 0; r < 2; ++r) {
                bv0[r] = *(const float4*)(B + (size_t)(kc + 2 * b_p[r]) * 128 + b_n[r]);
                bv1[r] = *(const float4*)(B + (size_t)(kc + 2 * b_p[r] + 1) * 128 + b_n[r]);
            }
        }

#pragma unroll
        for (int ks = 0; ks < 4; ++ks) {
            const int pb = ks * 8;
            unsigned aH[2][4], aL[2][4];
#pragma unroll
            for (int mt = 0; mt < 2; ++mt) {
                const int r0 = (wm + mt * 16 + g) * 36;
                const int r1 = r0 + 8 * 36;
                aH[mt][0] = cAH[r0 + pb + t];
                aH[mt][1] = cAH[r1 + pb + t];
                aH[mt][2] = cAH[r0 + pb + t + 4];
                aH[mt][3] = cAH[r1 + pb + t + 4];
                aL[mt][0] = cAL[r0 + pb + t];
                aL[mt][1] = cAL[r1 + pb + t];
                aL[mt][2] = cAL[r0 + pb + t + 4];
                aL[mt][3] = cAL[r1 + pb + t + 4];
            }
#pragma unroll
            for (int nt = 0; nt < 4; ++nt) {
                const int nb = wn + nt * 8 + g;
                const int j0 = (pb + t) * 136 + nb;
                const int j1 = (pb + t + 4) * 136 + nb;
                unsigned bH[2] = { cBH[j0], cBH[j1] };
                unsigned bL[2] = { cBL[j0], cBL[j1] };
#pragma unroll
                for (int mt = 0; mt < 2; ++mt) {
                    mma16(acc[mt][nt], aH[mt], bH);
                    mma16(acc[mt][nt], aL[mt], bH);
                    mma16(acc[mt][nt], aH[mt], bL);
                }
            }
        }

        if (hn) {
            unsigned* nb = smd + ((it + 1) & 1) * BUF_STRIDE;
#pragma unroll
            for (int r = 0; r < 4; ++r)
                stA(nb, nb + ASZ, ar_row[r], ar_kq[r], av[r]);
#pragma unroll
            for (int r = 0; r < 2; ++r)
                stB(nb + 2 * ASZ, nb + 2 * ASZ + BSZ, b_p[r], b_n[r], bv0[r], bv1[r]);
        }
        __syncthreads();
    }

    float* Cb = Cp + (size_t)m0 * 128;
    float lmax = 0.f;
#pragma unroll
    for (int mt = 0; mt < 2; ++mt)
#pragma unroll
        for (int nt = 0; nt < 4; ++nt) {
            const int r = wm + mt * 16 + g;
            const int c = wn + nt * 8 + t * 2;
            *(float2*)&Cb[(size_t)r * 128 + c] =
                make_float2(acc[mt][nt][0], acc[mt][nt][1]);
            *(float2*)&Cb[(size_t)(r + 8) * 128 + c] =
                make_float2(acc[mt][nt][2], acc[mt][nt][3]);
            if (maxSlot) {
#pragma unroll
                for (int i = 0; i < 4; ++i)
                    lmax = fmaxf(lmax, fabsf(acc[mt][nt][i]));
            }
        }
    if (maxSlot) {
#pragma unroll
        for (int o = 16; o > 0; o >>= 1)
            lmax = fmaxf(lmax, __shfl_xor_sync(0xFFFFFFFFu, lmax, o));
        if (lane == 0) atomicMax(maxSlot, __float_as_int(lmax));
    }
}

// ------------------------------ GEMM kernels ---------------------------------
struct GemmJob { const float* A; const float* B; float* C; int* slot; };

__global__ __launch_bounds__(512, 1)
void gemm_small3(GemmJob j0, GemmJob j1, GemmJob j2)
{
    GemmJob j = (blockIdx.z == 0) ? j0 : ((blockIdx.z == 1) ? j1 : j2);
    gemm_body_bf<0>(j.A, j.B, j.C, blockIdx.x, nullptr, nullptr, j.slot);
}

__global__ __launch_bounds__(512, 1)
void gemm_x1theta(const float* __restrict__ ZP, const float* __restrict__ th1,
                  float* __restrict__ T,
                  const float* __restrict__ U, const float* __restrict__ b0,
                  int* __restrict__ slot)
{
    gemm_body_bf<1>(ZP, th1, T, blockIdx.x, U, b0, slot);
}

// ------------------------ reduce / epilogue kernels --------------------------
__global__ void init_scales_k(int* s) { s[threadIdx.x] = 0; }

__global__ void reduce_msg_k(const float* __restrict__ P, const float* __restrict__ ew,
                             float* __restrict__ out, int* __restrict__ slot)
{
    const int i = blockIdx.x * 256 + threadIdx.x;
    float s = 0.f;
#pragma unroll
    for (int j = 0; j < 4; ++j) s += P[(size_t)j * (4096 * 128) + i];
    const float v = s * ew[i >> 7];
    out[i] = v;

    float m = fabsf(v);
#pragma unroll
    for (int o = 16; o > 0; o >>= 1)
        m = fmaxf(m, __shfl_xor_sync(0xFFFFFFFFu, m, o));
    __shared__ float wmax[8];
    if ((threadIdx.x & 31) == 0) wmax[threadIdx.x >> 5] = m;
    __syncthreads();
    if (threadIdx.x == 0) {
        float mm = wmax[0];
#pragma unroll
        for (int w = 1; w < 8; ++w) mm = fmaxf(mm, wmax[w]);
        atomicMax(slot, __float_as_int(mm));
    }
}

__global__ void fc_fused_k(const float* __restrict__ ZP, const float* __restrict__ U1,
                           const float* __restrict__ b1,
                           const float* __restrict__ state,
                           const float* __restrict__ fcw, const float* __restrict__ fcb,
                           float* __restrict__ out)
{
    const int n = blockIdx.x * 256 + threadIdx.x;
    const float4* u4  = (const float4*)(U1 + (size_t)n * 128);
    const float4* p04 = (const float4*)(ZP + (size_t)n * 128);
    const float4* p14 = (const float4*)(ZP + ZP_STRIDE + (size_t)n * 128);
    const float4* w4  = (const float4*)fcw;
    float s = 0.f;
#pragma unroll
    for (int i = 0; i < 32; ++i) {
        float4 u = u4[i], p0 = p04[i], p1 = p14[i], w = w4[i];
        float e[4] = { u.x + b1[4 * i],     u.y + b1[4 * i + 1],
                       u.z + b1[4 * i + 2], u.w + b1[4 * i + 3] };
        e[0] += p0.x; e[1] += p0.y; e[2] += p0.z; e[3] += p0.w;
        e[0] += p1.x; e[1] += p1.y; e[2] += p1.z; e[3] += p1.w;
        const float* ww = &w.x;
#pragma unroll
        for (int q = 0; q < 4; ++q) {
            float z = e[q];
            z = (z >= 0.f) ? z : 0.01f * z;
            z = (z >= 0.f) ? z : 0.01f * z;
            s += z * ww[q];
        }
    }
    out[n] = s + state[n] * fcw[128] + fcb[0];
}

// --------------------------------- launch ------------------------------------
extern "C" void kernel_launch(void* const* d_in, const int* in_sizes, int n_in,
                              void* d_out, int out_size)
{
    const float* xi   = (const float*)d_in[0];
    const float* x    = (const float*)d_in[1];
    const float* Ht   = (const float*)d_in[2];
    const float* Hs   = (const float*)d_in[3];
    const float* st   = (const float*)d_in[4];
    const float* w0   = (const float*)d_in[5];
    const float* th0  = (const float*)d_in[6];
    const float* ew0  = (const float*)d_in[7];
    const float* b0   = (const float*)d_in[8];
    const float* w1   = (const float*)d_in[9];
    const float* th1  = (const float*)d_in[10];
    const float* ew1  = (const float*)d_in[11];
    const float* b1   = (const float*)d_in[12];
    const float* fcw  = (const float*)d_in[13];
    const float* fcb  = (const float*)d_in[14];
    float* out = (float*)d_out;

    float *T, *U, *U1, *M, *MP, *ZP;
    int* SC;
    cudaGetSymbolAddress((void**)&T,  g_T);
    cudaGetSymbolAddress((void**)&U,  g_U);
    cudaGetSymbolAddress((void**)&U1, g_U1);
    cudaGetSymbolAddress((void**)&M,  g_msg);
    cudaGetSymbolAddress((void**)&MP, g_msgP);
    cudaGetSymbolAddress((void**)&ZP, g_ZP);
    cudaGetSymbolAddress((void**)&SC, g_scaleMax);

    cudaFuncSetAttribute(gemm_small3,  cudaFuncAttributeMaxDynamicSharedMemorySize, SM_BYTES);
    cudaFuncSetAttribute(gemm_x1theta, cudaFuncAttributeMaxDynamicSharedMemorySize, SM_BYTES);

    init_scales_k<<<1, 4>>>(SC);

    // small GEMMs: T = x@th0 (track max -> slot0), U = xi@w0, U1 = xi@w1
    GemmJob j0 = { x,  th0, T,  SC + 0   };
    GemmJob j1 = { xi, w0,  U,  nullptr  };
    GemmJob j2 = { xi, w1,  U1, nullptr  };
    gemm_small3<<<dim3(64, 1, 3), 512, SM_BYTES>>>(j0, j1, j2);

    // ---- layer 0 ----
    gemm_i8<false><<<dim3(32, 4), 512>>>(Hs, T, MP, 8192, 64, SC + 0);
    reduce_msg_k<<<2048, 256>>>(MP, ew0, M, SC + 1);
    gemm_i8<true ><<<dim3(64, 2), 512>>>(Ht, M, ZP, 8192, 64, SC + 1);

    // ---- layer 1 ----  (X1 built inside the theta GEMM; T1 max -> slot2)
    gemm_x1theta<<<64, 512, SM_BYTES>>>(ZP, th1, T, U, b0, SC + 2);
    gemm_i8<false><<<dim3(32, 4), 512>>>(Hs, T, MP, 8192, 64, SC + 2);
    reduce_msg_k<<<2048, 256>>>(MP, ew1, M, SC + 3);
    gemm_i8<true ><<<dim3(64, 2), 512>>>(Ht, M, ZP, 8192, 64, SC + 3);

    // ---- head ----
    fc_fused_k<<<32, 256>>>(ZP, U1, b1, st, fcw, fcb, out);
}

// round 17
// speedup vs baseline: 2.6773x; 2.6773x over previous
#include <cuda_runtime.h>
#include <cuda_bf16.h>

#define JAX_PARTITIONABLE 1

// ---------------- scratch (__device__ globals; no allocation) ----------------
__device__ float g_T[8192 * 128];          // X_in @ theta
__device__ float g_U[8192 * 128];          // xi @ w_trans0
__device__ float g_U1[8192 * 128];         // xi @ w_trans1
__device__ float g_msg[4096 * 128];        // edge messages (ew-scaled)
__device__ float g_msgP[4 * 4096 * 128];   // split-K partials for Hs GEMM (S=4)
__device__ float g_ZP[2 * 8192 * 128];     // split-K partials for Ht^T GEMM (S=2)

static const int ZP_STRIDE = 64 * 128 * 128;   // floats between Z partials

// ------------------------------- helpers ------------------------------------
__device__ __forceinline__ unsigned rotl32(unsigned v, int s) {
    return __funnelshift_l(v, v, s);
}

// bf16 2-way split of a k-pair (f0 = even k, f1 = odd k) -> packed hi, lo u32.
__device__ __forceinline__ void split_pair(float f0, float f1,
                                           unsigned& H, unsigned& L) {
    __nv_bfloat162 h = __floats2bfloat162_rn(f0, f1);
    float r0 = f0 - __bfloat162float(h.x);
    float r1 = f1 - __bfloat162float(h.y);
    __nv_bfloat162 l = __floats2bfloat162_rn(r0, r1);
    H = *reinterpret_cast<unsigned*>(&h);
    L = *reinterpret_cast<unsigned*>(&l);
}

// m16n8k16 bf16 mma, fp32 accumulate
__device__ __forceinline__ void mma16(float c[4], const unsigned a[4], const unsigned b[2]) {
    asm("mma.sync.aligned.m16n8k16.row.col.f32.bf16.bf16.f32 "
        "{%0,%1,%2,%3},{%4,%5,%6,%7},{%8,%9},{%0,%1,%2,%3};"
        : "+f"(c[0]), "+f"(c[1]), "+f"(c[2]), "+f"(c[3])
        : "r"(a[0]), "r"(a[1]), "r"(a[2]), "r"(a[3]), "r"(b[0]), "r"(b[1]));
}

// JAX threefry2x32, key = (0, 42). Random bits for flat element j of (8192,128).
__device__ __forceinline__ unsigned jax_dropout_bits(unsigned j) {
    const unsigned k0 = 0u, k1 = 42u;
    const unsigned ks2 = k0 ^ k1 ^ 0x1BD11BDAu;
    unsigned x0, x1;
#if JAX_PARTITIONABLE
    x0 = 0u + k0;
    x1 = j + k1;
#else
    const unsigned HALF = 524288u;
    unsigned i = (j < HALF) ? j : (j - HALF);
    x0 = i + k0;
    x1 = (i + HALF) + k1;
#endif
#define TFR(r) do { x0 += x1; x1 = rotl32(x1, (r)); x1 ^= x0; } while (0)
    TFR(13); TFR(15); TFR(26); TFR(6);   x0 += k1;  x1 += ks2 + 1u;
    TFR(17); TFR(29); TFR(16); TFR(24);  x0 += ks2; x1 += k0 + 2u;
    TFR(13); TFR(15); TFR(26); TFR(6);   x0 += k0;  x1 += k1 + 3u;
    TFR(17); TFR(29); TFR(16); TFR(24);  x0 += k1;  x1 += ks2 + 4u;
    TFR(13); TFR(15); TFR(26); TFR(6);   x0 += ks2; x1 += k0 + 5u;
#undef TFR
#if JAX_PARTITIONABLE
    return x0 ^ x1;
#else
    return (j < 524288u) ? x0 : x1;
#endif
}

// build one X1 float4 (fused reduce_x1: partials + U + bias, lrelu, dropout)
__device__ __forceinline__ float4 make_x1(const float* __restrict__ ZP,
                                          const float* __restrict__ U,
                                          const float* __restrict__ bias,
                                          int idx /*flat, mult of 4*/, int col)
{
    float4 u  = *(const float4*)(U + idx);
    float4 p0 = *(const float4*)(ZP + idx);
    float4 p1 = *(const float4*)(ZP + ZP_STRIDE + idx);
    float e[4] = { u.x + bias[col],     u.y + bias[col + 1],
                   u.z + bias[col + 2], u.w + bias[col + 3] };
    e[0] += p0.x; e[1] += p0.y; e[2] += p0.z; e[3] += p0.w;
    e[0] += p1.x; e[1] += p1.y; e[2] += p1.z; e[3] += p1.w;
    float4 r;
    float* rr = &r.x;
#pragma unroll
    for (int q = 0; q < 4; ++q) {
        float z = e[q];
        z = (z >= 0.f) ? z : 0.01f * z;                       // lrelu
        unsigned bits = jax_dropout_bits((unsigned)(idx + q));
        rr[q] = (bits & 0x80000000u) ? 0.f : (z + z);         // dropout p=.5
    }
    return r;
}

// ====================== 3-term bf16-split GEMM (k64/iter) ====================
static const int ASZ = 4608, BSZ = 4352;
static const int BUF_STRIDE = 2 * ASZ + 2 * BSZ;   // 17920 u32
static const int SM_BYTES = BUF_STRIDE * 2 * 4;    // 143360 B

template <bool TRANS_A>
__device__ __forceinline__ float4 loadA(const float* __restrict__ A, int lda,
                                        int m0, int kc, int row, int kq) {
    if (TRANS_A) {
        const float* p = A + (size_t)(kc + kq * 4) * lda + m0 + row;
        float4 v;
        v.x = p[0];
        v.y = p[(size_t)lda];
        v.z = p[2 * (size_t)lda];
        v.w = p[3 * (size_t)lda];
        return v;
    } else {
        return *(const float4*)(A + (size_t)(m0 + row) * lda + kc + kq * 4);
    }
}

__device__ __forceinline__ void stA(unsigned* __restrict__ AsH,
                                    unsigned* __restrict__ AsL,
                                    int row, int kq, float4 v) {
    unsigned h0, l0, h1, l1;
    split_pair(v.x, v.y, h0, l0);
    split_pair(v.z, v.w, h1, l1);
    *(uint2*)&AsH[row * 36 + 2 * kq] = make_uint2(h0, h1);
    *(uint2*)&AsL[row * 36 + 2 * kq] = make_uint2(l0, l1);
}

__device__ __forceinline__ void stB(unsigned* __restrict__ BsH,
                                    unsigned* __restrict__ BsL,
                                    int p, int n, float4 r0, float4 r1) {
    unsigned h[4], l[4];
    split_pair(r0.x, r1.x, h[0], l[0]);
    split_pair(r0.y, r1.y, h[1], l[1]);
    split_pair(r0.z, r1.z, h[2], l[2]);
    split_pair(r0.w, r1.w, h[3], l[3]);
    *(uint4*)&BsH[p * 136 + n] = make_uint4(h[0], h[1], h[2], h[3]);
    *(uint4*)&BsL[p * 136 + n] = make_uint4(l[0], l[1], l[2], l[3]);
}

// A_SRC: 0 = plain global (loadA), 1 = fused X1 build (reduce+lrelu+dropout)
template <bool TRANS_A, int A_SRC>
__device__ __forceinline__ void gemm_body_bf(
    const float* __restrict__ A, const float* __restrict__ B,
    float* __restrict__ Cp, int lda, int k_iters, int mblk, int split, int gx,
    const float* __restrict__ xU, const float* __restrict__ xb)
{
    extern __shared__ unsigned sm[];
    const int tid = threadIdx.x;
    const int lane = tid & 31;
    const int wid = tid >> 5;              // 0..15
    const int wm = (wid & 3) * 32;
    const int wn = (wid >> 2) * 32;
    const int g = lane >> 2;               // 0..7
    const int t = lane & 3;                // 0..3
    const int m0 = mblk * 128;
    const int k00 = split * k_iters * 64;

    int ar_row[4], ar_kq[4];
#pragma unroll
    for (int r = 0; r < 4; ++r) {
        int task = tid + r * 512;
        if (TRANS_A) { ar_row[r] = task & 127; ar_kq[r] = task >> 7; }
        else         { ar_row[r] = task >> 4;  ar_kq[r] = task & 15; }
    }
    int b_p[2], b_n[2];
#pragma unroll
    for (int r = 0; r < 2; ++r) {
        int task = tid + r * 512;
        b_p[r] = task >> 5;
        b_n[r] = (task & 31) * 4;
    }

    float acc[2][4][4];
#pragma unroll
    for (int mt = 0; mt < 2; ++mt)
#pragma unroll
        for (int nt = 0; nt < 4; ++nt)
#pragma unroll
            for (int i = 0; i < 4; ++i) acc[mt][nt][i] = 0.f;

    float4 av[4], bv0[2], bv1[2];

    int kc = k00;
#pragma unroll
    for (int r = 0; r < 4; ++r) {
        if (A_SRC == 1)
            av[r] = make_x1(A, xU, xb,
                            (m0 + ar_row[r]) * 128 + kc + ar_kq[r] * 4,
                            kc + ar_kq[r] * 4);
        else
            av[r] = loadA<TRANS_A>(A, lda, m0, kc, ar_row[r], ar_kq[r]);
    }
#pragma unroll
    for (int r = 0; r < 2; ++r) {
        bv0[r] = *(const float4*)(B + (size_t)(kc + 2 * b_p[r]) * 128 + b_n[r]);
        bv1[r] = *(const float4*)(B + (size_t)(kc + 2 * b_p[r] + 1) * 128 + b_n[r]);
    }
#pragma unroll
    for (int r = 0; r < 4; ++r) stA(sm, sm + ASZ, ar_row[r], ar_kq[r], av[r]);
#pragma unroll
    for (int r = 0; r < 2; ++r)
        stB(sm + 2 * ASZ, sm + 2 * ASZ + BSZ, b_p[r], b_n[r], bv0[r], bv1[r]);
    __syncthreads();

    for (int it = 0; it < k_iters; ++it) {
        const unsigned* cur = sm + (it & 1) * BUF_STRIDE;
        const unsigned* cAH = cur;
        const unsigned* cAL = cur + ASZ;
        const unsigned* cBH = cur + 2 * ASZ;
        const unsigned* cBL = cur + 2 * ASZ + BSZ;
        const bool hn = (it + 1 < k_iters);

        if (hn) {
            kc = k00 + (it + 1) * 64;
#pragma unroll
            for (int r = 0; r < 4; ++r) {
                if (A_SRC == 1)
                    av[r] = make_x1(A, xU, xb,
                                    (m0 + ar_row[r]) * 128 + kc + ar_kq[r] * 4,
                                    kc + ar_kq[r] * 4);
                else
                    av[r] = loadA<TRANS_A>(A, lda, m0, kc, ar_row[r], ar_kq[r]);
            }
#pragma unroll
            for (int r = 0; r < 2; ++r) {
                bv0[r] = *(const float4*)(B + (size_t)(kc + 2 * b_p[r]) * 128 + b_n[r]);
                bv1[r] = *(const float4*)(B + (size_t)(kc + 2 * b_p[r] + 1) * 128 + b_n[r]);
            }
        }

#pragma unroll
        for (int ks = 0; ks < 4; ++ks) {
            const int pb = ks * 8;
            unsigned aH[2][4], aL[2][4];
#pragma unroll
            for (int mt = 0; mt < 2; ++mt) {
                const int r0 = (wm + mt * 16 + g) * 36;
                const int r1 = r0 + 8 * 36;
                aH[mt][0] = cAH[r0 + pb + t];
                aH[mt][1] = cAH[r1 + pb + t];
                aH[mt][2] = cAH[r0 + pb + t + 4];
                aH[mt][3] = cAH[r1 + pb + t + 4];
                aL[mt][0] = cAL[r0 + pb + t];
                aL[mt][1] = cAL[r1 + pb + t];
                aL[mt][2] = cAL[r0 + pb + t + 4];
                aL[mt][3] = cAL[r1 + pb + t + 4];
            }
#pragma unroll
            for (int nt = 0; nt < 4; ++nt) {
                const int nb = wn + nt * 8 + g;
                const int j0 = (pb + t) * 136 + nb;
                const int j1 = (pb + t + 4) * 136 + nb;
                unsigned bH[2] = { cBH[j0], cBH[j1] };
                unsigned bL[2] = { cBL[j0], cBL[j1] };
#pragma unroll
                for (int mt = 0; mt < 2; ++mt) {
                    mma16(acc[mt][nt], aH[mt], bH);
                    mma16(acc[mt][nt], aL[mt], bH);
                    mma16(acc[mt][nt], aH[mt], bL);
                }
            }
        }

        if (hn) {
            unsigned* nb = sm + ((it + 1) & 1) * BUF_STRIDE;
#pragma unroll
            for (int r = 0; r < 4; ++r)
                stA(nb, nb + ASZ, ar_row[r], ar_kq[r], av[r]);
#pragma unroll
            for (int r = 0; r < 2; ++r)
                stB(nb + 2 * ASZ, nb + 2 * ASZ + BSZ, b_p[r], b_n[r], bv0[r], bv1[r]);
        }
        __syncthreads();
    }

    float* Cb = Cp + (size_t)split * gx * (128 * 128) + (size_t)m0 * 128;
#pragma unroll
    for (int mt = 0; mt < 2; ++mt)
#pragma unroll
        for (int nt = 0; nt < 4; ++nt) {
            const int r = wm + mt * 16 + g;
            const int c = wn + nt * 8 + t * 2;
            *(float2*)&Cb[(size_t)r * 128 + c] =
                make_float2(acc[mt][nt][0], acc[mt][nt][1]);
            *(float2*)&Cb[(size_t)(r + 8) * 128 + c] =
                make_float2(acc[mt][nt][2], acc[mt][nt][3]);
        }
}

// ------------------------------ GEMM kernels ---------------------------------
template <bool TRANS_A>
__global__ __launch_bounds__(512, 1)
void gemm_big(const float* __restrict__ A, const float* __restrict__ B,
              float* __restrict__ Cp, int lda, int k_iters)
{
    gemm_body_bf<TRANS_A, 0>(A, B, Cp, lda, k_iters,
                             blockIdx.x, blockIdx.y, gridDim.x, nullptr, nullptr);
}

struct GemmJob { const float* A; const float* B; float* C; };

// single small GEMM (T = x @ th0), grid 64
__global__ __launch_bounds__(512, 1)
void gemm_small1(const float* __restrict__ A, const float* __restrict__ B,
                 float* __restrict__ C)
{
    gemm_body_bf<false, 0>(A, B, C, 128, 2, blockIdx.x, 0, 64, nullptr, nullptr);
}

// layer-0 Hs GEMM (blocks 0..127, 32 tiles x 4 splits) + ride-along U/U1 small
// GEMMs on blocks 128..147 (the 20 SMs the 128-CTA grid leaves idle).
__global__ __launch_bounds__(512, 1)
void gemm_hs_ride(const float* __restrict__ Hs, const float* __restrict__ T,
                  float* __restrict__ MP, GemmJob jU, GemmJob jU1)
{
    const int bid = blockIdx.x;
    if (bid < 128) {
        gemm_body_bf<false, 0>(Hs, T, MP, 8192, 32,
                               bid & 31, bid >> 5, 32, nullptr, nullptr);
    } else {
        // 128 side tiles: t in [0,64) -> U, [64,128) -> U1
        for (int tIdx = bid - 128; tIdx < 128; tIdx += 20) {
            const GemmJob j = (tIdx < 64) ? jU : jU1;
            gemm_body_bf<false, 0>(j.A, j.B, j.C, 128, 2,
                                   tIdx & 63, 0, 64, nullptr, nullptr);
        }
    }
}

// layer-1 theta GEMM with fused X1 construction (A = lrelu/dropout(ZP+U+b0))
__global__ __launch_bounds__(512, 1)
void gemm_x1theta(const float* __restrict__ ZP, const float* __restrict__ th1,
                  float* __restrict__ T,
                  const float* __restrict__ U, const float* __restrict__ b0)
{
    gemm_body_bf<false, 1>(ZP, th1, T, 128, 2, blockIdx.x, 0, 64, U, b0);
}

// ------------------------ reduce / epilogue kernels --------------------------
__global__ void reduce_msg_k(const float* __restrict__ P, const float* __restrict__ ew,
                             float* __restrict__ out)
{
    const int i = blockIdx.x * 256 + threadIdx.x;
    float s = 0.f;
#pragma unroll
    for (int j = 0; j < 4; ++j) s += P[(size_t)j * (4096 * 128) + i];
    out[i] = s * ew[i >> 7];
}

// fc with fused reduce_x2 (X2 built on the fly from Z partials)
__global__ void fc_fused_k(const float* __restrict__ ZP, const float* __restrict__ U1,
                           const float* __restrict__ b1,
                           const float* __restrict__ state,
                           const float* __restrict__ fcw, const float* __restrict__ fcb,
                           float* __restrict__ out)
{
    const int n = blockIdx.x * 128 + threadIdx.x;
    const float4* u4  = (const float4*)(U1 + (size_t)n * 128);
    const float4* p04 = (const float4*)(ZP + (size_t)n * 128);
    const float4* p14 = (const float4*)(ZP + ZP_STRIDE + (size_t)n * 128);
    const float4* w4  = (const float4*)fcw;
    float s = 0.f;
#pragma unroll
    for (int i = 0; i < 32; ++i) {
        float4 u = u4[i], p0 = p04[i], p1 = p14[i], w = w4[i];
        float e[4] = { u.x + b1[4 * i],     u.y + b1[4 * i + 1],
                       u.z + b1[4 * i + 2], u.w + b1[4 * i + 3] };
        e[0] += p0.x; e[1] += p0.y; e[2] += p0.z; e[3] += p0.w;
        e[0] += p1.x; e[1] += p1.y; e[2] += p1.z; e[3] += p1.w;
        const float* ww = &w.x;
#pragma unroll
        for (int q = 0; q < 4; ++q) {
            float z = e[q];
            z = (z >= 0.f) ? z : 0.01f * z;   // conv lrelu
            z = (z >= 0.f) ? z : 0.01f * z;   // forward lrelu
            s += z * ww[q];
        }
    }
    out[n] = s + state[n] * fcw[128] + fcb[0];
}

// --------------------------------- launch ------------------------------------
extern "C" void kernel_launch(void* const* d_in, const int* in_sizes, int n_in,
                              void* d_out, int out_size)
{
    const float* xi   = (const float*)d_in[0];
    const float* x    = (const float*)d_in[1];
    const float* Ht   = (const float*)d_in[2];
    const float* Hs   = (const float*)d_in[3];
    const float* st   = (const float*)d_in[4];
    const float* w0   = (const float*)d_in[5];
    const float* th0  = (const float*)d_in[6];
    const float* ew0  = (const float*)d_in[7];
    const float* b0   = (const float*)d_in[8];
    const float* w1   = (const float*)d_in[9];
    const float* th1  = (const float*)d_in[10];
    const float* ew1  = (const float*)d_in[11];
    const float* b1   = (const float*)d_in[12];
    const float* fcw  = (const float*)d_in[13];
    const float* fcb  = (const float*)d_in[14];
    float* out = (float*)d_out;

    float *T, *U, *U1, *M, *MP, *ZP;
    cudaGetSymbolAddress((void**)&T,  g_T);
    cudaGetSymbolAddress((void**)&U,  g_U);
    cudaGetSymbolAddress((void**)&U1, g_U1);
    cudaGetSymbolAddress((void**)&M,  g_msg);
    cudaGetSymbolAddress((void**)&MP, g_msgP);
    cudaGetSymbolAddress((void**)&ZP, g_ZP);

    cudaFuncSetAttribute(gemm_big<false>, cudaFuncAttributeMaxDynamicSharedMemorySize, SM_BYTES);
    cudaFuncSetAttribute(gemm_big<true>,  cudaFuncAttributeMaxDynamicSharedMemorySize, SM_BYTES);
    cudaFuncSetAttribute(gemm_small1,     cudaFuncAttributeMaxDynamicSharedMemorySize, SM_BYTES);
    cudaFuncSetAttribute(gemm_hs_ride,    cudaFuncAttributeMaxDynamicSharedMemorySize, SM_BYTES);
    cudaFuncSetAttribute(gemm_x1theta,    cudaFuncAttributeMaxDynamicSharedMemorySize, SM_BYTES);

    // T = x @ th0 (blocks layer 0; U/U1 ride inside the first big GEMM)
    gemm_small1<<<64, 512, SM_BYTES>>>(x, th0, T);

    // ---- layer 0 ----
    GemmJob jU  = { xi, w0, U  };
    GemmJob jU1 = { xi, w1, U1 };
    gemm_hs_ride<<<148, 512, SM_BYTES>>>(Hs, T, MP, jU, jU1);   // big0 + U + U1
    reduce_msg_k<<<2048, 256>>>(MP, ew0, M);
    gemm_big<true ><<<dim3(64, 2), 512, SM_BYTES>>>(Ht, M, ZP, 8192, 32);

    // ---- layer 1 ----  (X1 built inside the theta GEMM's staging)
    gemm_x1theta<<<64, 512, SM_BYTES>>>(ZP, th1, T, U, b0);
    gemm_big<false><<<dim3(32, 4), 512, SM_BYTES>>>(Hs, T, MP, 8192, 32);
    reduce_msg_k<<<2048, 256>>>(MP, ew1, M);
    gemm_big<true ><<<dim3(64, 2), 512, SM_BYTES>>>(Ht, M, ZP, 8192, 32);

    // ---- head ----  (X2 built inside fc)
    fc_fused_k<<<64, 128>>>(ZP, U1, b1, st, fcw, fcb, out);
}